// round 2
// baseline (speedup 1.0000x reference)
#include <cuda_runtime.h>
#include <cuda_bf16.h>

// y[b][t][c] = d[c] * y[b][t-1][c] + x[b][t][c],  y[b][0][c] = x[b][0][c]
// x: [8, 4096, 1024] fp32, d: [1024] fp32.
//
// Strategy: one block per (batch, 32-channel tile). Block walks time in
// segments of 256 steps (8 warps x 32 steps/thread). Per segment:
//   1) each thread loads its 32 x-values into registers (prefetched one
//      segment ahead) and computes its chunk carry  c = sum d^(31-i) x_i
//   2) one __syncthreads; every thread folds the 8 chunk carries with ratio
//      d^32 (reads from a parity-double-buffered smem array), capturing its
//      own prefix and the new block carry (kept in a register by everyone)
//   3) each thread re-runs the 32-step scan from its prefix using the
//      register-resident x values and stores y (coalesced 128B/warp)
// x is read from HBM exactly once, y written once: 256 MiB total traffic.

#define BB    8
#define TT    4096
#define CC    1024
#define CT    32                 // channels per block (= warp lanes)
#define NW    8                  // time-warps per block
#define STEPS 32                 // timesteps per thread per segment
#define SEG   (NW * STEPS)       // 256 timesteps per segment
#define NSEG  (TT / SEG)         // 16 segments

__global__ void __launch_bounds__(CT * NW, 2)
cummulsum_kernel(const float* __restrict__ x,
                 const float* __restrict__ d,
                 float* __restrict__ y)
{
    __shared__ float scarry[2][NW][CT];

    const int lane = threadIdx.x;            // channel lane 0..31
    const int ty   = threadIdx.y;            // time-warp 0..7
    const int c    = blockIdx.x * CT + lane; // channel
    const int b    = blockIdx.y;             // batch

    const float dd = d[c];
    // dS = d^STEPS = d^32 via 5 squarings
    float dS = dd;
    #pragma unroll
    for (int i = 0; i < 5; i++) dS = dS * dS;

    const float* xbase = x + ((size_t)b * TT) * CC + c;
    float*       ybase = y + ((size_t)b * TT) * CC + c;

    float xa[STEPS], xn[STEPS];

    // Load segment 0
    {
        const float* p0 = xbase + (size_t)(ty * STEPS) * CC;
        #pragma unroll
        for (int i = 0; i < STEPS; i++) xa[i] = p0[(size_t)i * CC];
    }

    float bc = 0.0f;   // block carry: y value just before this segment

    for (int s = 0; s < NSEG; s++) {
        // Prefetch next segment (independent of the carry chain)
        if (s + 1 < NSEG) {
            const float* p1 = xbase + (size_t)((s + 1) * SEG + ty * STEPS) * CC;
            #pragma unroll
            for (int i = 0; i < STEPS; i++) xn[i] = p1[(size_t)i * CC];
        }

        // Pass 1: chunk carry (scan of 32 steps with y_in = 0)
        float cr = xa[0];
        #pragma unroll
        for (int i = 1; i < STEPS; i++) cr = fmaf(dd, cr, xa[i]);

        const int par = s & 1;
        scarry[par][ty][lane] = cr;
        __syncthreads();

        // Fold: every thread walks all 8 chunk carries.
        //   p after folding chunks 0..w  ==  prefix for time-warp w+1
        //   p after folding all 8        ==  next block carry (in a register)
        float p   = bc;
        float myp = bc;   // prefix for ty==0
        #pragma unroll
        for (int w = 0; w < NW; w++) {
            const float cw = scarry[par][w][lane];
            p = fmaf(dS, p, cw);
            if (w == ty - 1) myp = p;
        }
        bc = p;

        // Pass 2: re-scan from prefix using register-resident x, store y
        float yv = myp;
        float* po = ybase + (size_t)(s * SEG + ty * STEPS) * CC;
        #pragma unroll
        for (int i = 0; i < STEPS; i++) {
            yv = fmaf(dd, yv, xa[i]);
            po[(size_t)i * CC] = yv;
        }

        // Rotate prefetch buffer
        #pragma unroll
        for (int i = 0; i < STEPS; i++) xa[i] = xn[i];
    }
}

extern "C" void kernel_launch(void* const* d_in, const int* in_sizes, int n_in,
                              void* d_out, int out_size)
{
    const float* x = (const float*)d_in[0];
    const float* d = (const float*)d_in[1];
    // Robustness: identify by size (x is 33.5M elems, d is 1024)
    if (n_in >= 2 && in_sizes[0] < in_sizes[1]) {
        x = (const float*)d_in[1];
        d = (const float*)d_in[0];
    }
    float* y = (float*)d_out;

    dim3 grid(CC / CT, BB);   // (32, 8) = 256 blocks
    dim3 block(CT, NW);       // (32, 8) = 256 threads
    cummulsum_kernel<<<grid, block>>>(x, d, y);
}